// round 5
// baseline (speedup 1.0000x reference)
#include <cuda_runtime.h>

// BoxBlur 13x13 reflect, (8,64,512,512) fp32. Separable, sliding-window.
// CTA = 16-row x 512-wide stripe, 512 threads, 3 CTAs/SM.
// Pass 1: vertical running 13-sum, 13-deep register ring (1 LDG/output).
// Pass 2: horizontal sliding 13-sums, 16-wide segments, STS.128 staging,
//         float4 coalesced flush. Only 2 __syncthreads per tile.

#define Wd 512
#define Hd 512
#define TY 16
#define NT 512
#define PW 513            // vs stride: conflict-free for rl + {0,16} lane map
#define OW 516            // os stride: float4-aligned, conflict-free
#define KHALF 6

#define SMEM_FLOATS (TY * PW + TY * OW)
#define SMEM_BYTES  (SMEM_FLOATS * 4)       // 65,856 B -> 3 CTAs/SM

__device__ __forceinline__ int reflect_i(int i, int n) {
    if (i < 0) i = -i;
    if (i >= n) i = 2 * n - 2 - i;
    return i;
}

__global__ __launch_bounds__(NT, 3)
void boxblur5(const float* __restrict__ in,
              const float* __restrict__ kern,
              float* __restrict__ out) {
    extern __shared__ float sm[];
    float* __restrict__ vs = sm;             // [TY][PW]  vertical 13-sums
    float* __restrict__ os = sm + TY * PW;   // [TY][OW]  output staging

    const int ytile = blockIdx.x;
    const int plane = blockIdx.y;
    const int y0 = ytile * TY;
    const float* __restrict__ ip = in  + (size_t)plane * (Hd * Wd);
    float*       __restrict__ op = out + (size_t)plane * (Hd * Wd);
    const int t = threadIdx.x;               // 0..511
    const float k0 = kern[0];                // 1/169

    // ---- Pass 1: vertical running 13-sum, thread t = column t, reg ring ----
    // Row read at step jj is y0 + jj - KHALF; output row j = jj - 12 is
    // written when the window [j-6, j+6] = rows read at jj-12..jj is complete.
    {
        float ring[13];
        float s = 0.0f;
        #pragma unroll
        for (int jj = 0; jj < TY + 12; jj++) {          // 28 row reads
            const int gy = reflect_i(y0 + jj - KHALF, Hd);
            const float v = ip[gy * Wd + t];            // coalesced LDG.32
            s += v;
            if (jj >= 12) {
                vs[(jj - 12) * PW + t] = s;
                s -= ring[(jj - 12) % 13];
            }
            ring[jj % 13] = v;
        }
    }
    __syncthreads();

    // ---- Pass 2: horizontal sliding 13-sums, 16-wide segment per thread ----
    {
        const int rl  = t & 15;         // row 0..15
        const int seg = t >> 4;         // 0..31
        const int xb  = seg * 16;
        const float* __restrict__ vrow = vs + rl * PW;
        float* __restrict__ orow = os + rl * OW;

        float ring[13];
        float s = 0.0f;
        #pragma unroll
        for (int k = 0; k < 13; k++) {
            const float v = vrow[reflect_i(xb - KHALF + k, Wd)];
            ring[k] = v;
            s += v;
        }
        float4 acc;
        #pragma unroll
        for (int i = 0; i < 16; i++) {
            const float o = s * k0;
            if ((i & 3) == 0)      acc.x = o;
            else if ((i & 3) == 1) acc.y = o;
            else if ((i & 3) == 2) acc.z = o;
            else {
                acc.w = o;
                *(float4*)&orow[xb + i - 3] = acc;      // STS.128
            }
            const float v = vrow[reflect_i(xb + i + KHALF + 1, Wd)];
            s += v - ring[i % 13];
            ring[i % 13] = v;
        }
    }
    __syncthreads();

    // ---- Flush: 16 rows, float4 coalesced ----
    {
        const int g   = t & 127;        // float4 column group
        const int rb  = t >> 7;         // 0..3
        #pragma unroll
        for (int k = 0; k < 4; k++) {
            const int row = rb + k * 4;
            const float4 v4 = *(const float4*)&os[row * OW + 4 * g];  // LDS.128
            *(float4*)&op[(size_t)(y0 + row) * Wd + 4 * g] = v4;      // STG.128
        }
    }
}

extern "C" void kernel_launch(void* const* d_in, const int* in_sizes, int n_in,
                              void* d_out, int out_size) {
    const float* input  = (const float*)d_in[0];   // (8,64,512,512) fp32
    const float* kernel = (const float*)d_in[1];   // (1,13,13) fp32 uniform
    float* out = (float*)d_out;

    cudaFuncSetAttribute(boxblur5, cudaFuncAttributeMaxDynamicSharedMemorySize,
                         SMEM_BYTES);

    dim3 grid(Hd / TY, 8 * 64);    // (32 y-tiles, 512 planes)
    boxblur5<<<grid, NT, SMEM_BYTES>>>(input, kernel, out);
}